// round 4
// baseline (speedup 1.0000x reference)
#include <cuda_runtime.h>
#include <cuda_bf16.h>

// QuantumFeatureMap closed form: t_q = cos(1.57*x_q), row outputs:
//   [t1t2t3, t0t1, t0t1t2, t0t1t2t3, t0t2t3, t0t3, t0, t2, t2t3, t3]
//
// R3 -> R4: no shared memory, no barrier. Each thread owns 2 adjacent rows:
//   loads  : x[2i], x[2i+1]      -> 32B contiguous per thread, 1KB per warp
//   stores : out[10*2i .. +20)   -> 80B contiguous per thread, 5x STG.128
// Chain is LDG -> MUFU/FMA -> STG, hidden by high occupancy (no smem, ~40 regs).

#define QFM_ALPHA 1.57f
#define QFM_BLOCK 256

__global__ void __launch_bounds__(QFM_BLOCK)
qfm_kernel(const float4* __restrict__ x, float4* __restrict__ out)
{
    const int i = blockIdx.x * QFM_BLOCK + threadIdx.x;   // row-pair index

    // Two adjacent rows, front-batched loads (MLP=2, contiguous per warp).
    float4 va = x[2 * i];
    float4 vb = x[2 * i + 1];

    // Row A
    float a0 = __cosf(QFM_ALPHA * va.x);
    float a1 = __cosf(QFM_ALPHA * va.y);
    float a2 = __cosf(QFM_ALPHA * va.z);
    float a3 = __cosf(QFM_ALPHA * va.w);
    // Row B
    float b0 = __cosf(QFM_ALPHA * vb.x);
    float b1 = __cosf(QFM_ALPHA * vb.y);
    float b2 = __cosf(QFM_ALPHA * vb.z);
    float b3 = __cosf(QFM_ALPHA * vb.w);

    float a01 = a0 * a1, a23 = a2 * a3;
    float b01 = b0 * b1, b23 = b2 * b3;

    // 20 outputs packed into 5 float4, written to a contiguous 80B span.
    float4* o = out + (size_t)i * 5;
    o[0] = make_float4(a1 * a23, a01, a01 * a2, a01 * a23);
    o[1] = make_float4(a0 * a23, a0 * a3, a0, a2);
    o[2] = make_float4(a23, a3, b1 * b23, b01);
    o[3] = make_float4(b01 * b2, b01 * b23, b0 * b23, b0 * b3);
    o[4] = make_float4(b0, b2, b23, b3);
}

extern "C" void kernel_launch(void* const* d_in, const int* in_sizes, int n_in,
                              void* d_out, int out_size)
{
    const float4* x = (const float4*)d_in[0];
    float4* out = (float4*)d_out;

    const int n_rows = in_sizes[0] / 4;                 // 1048576
    const int grid = n_rows / (2 * QFM_BLOCK);          // 2048 blocks

    qfm_kernel<<<grid, QFM_BLOCK>>>(x, out);
}

// round 5
// speedup vs baseline: 1.5598x; 1.5598x over previous
#include <cuda_runtime.h>
#include <cuda_bf16.h>

// QuantumFeatureMap closed form: t_q = cos(1.57*x_q), row outputs:
//   [t1t2t3, t0t1, t0t1t2, t0t1t2t3, t0t2t3, t0t3, t0, t2, t2t3, t3]
//
// R4 -> R5: back to smem-staged coalesced stores (R2 layout), but:
//   - single-wave persistent grid (1024 CTAs, 4 tiles each) -> no wave transitions
//   - warp-local staging + __syncwarp (no block barrier coupling)
//   - depth-2 pipelined loads across tiles (MLP_p1 = 2)

#define QFM_ALPHA 1.57f
#define QFM_BLOCK 256
#define QFM_ITERS 4

__global__ void __launch_bounds__(QFM_BLOCK)
qfm_kernel(const float4* __restrict__ x, float4* __restrict__ out)
{
    __shared__ __align__(16) float s[QFM_BLOCK * 10];      // 10240 B

    const int tid  = threadIdx.x;
    const int warp = tid >> 5;
    const int lane = tid & 31;

    float*  ws  = s + warp * 320;           // this warp's 32 rows * 10 floats
    float4* wsv = (float4*)ws;              // 80 float4
    float2* wsp = (float2*)(ws + lane * 10);// this lane's row (40B, 8B aligned)

    const int tile0 = blockIdx.x * QFM_ITERS;

    // Pipeline prologue: first tile's load in flight.
    float4 v = x[(size_t)tile0 * QFM_BLOCK + tid];

    #pragma unroll
    for (int it = 0; it < QFM_ITERS; ++it) {
        // Issue next tile's load before consuming this one (MLP across tiles).
        float4 vn;
        if (it + 1 < QFM_ITERS)
            vn = x[(size_t)(tile0 + it + 1) * QFM_BLOCK + tid];

        float t0 = __cosf(QFM_ALPHA * v.x);
        float t1 = __cosf(QFM_ALPHA * v.y);
        float t2 = __cosf(QFM_ALPHA * v.z);
        float t3 = __cosf(QFM_ALPHA * v.w);

        float t01 = t0 * t1;
        float t23 = t2 * t3;

        wsp[0] = make_float2(t1 * t23, t01);        // out0, out1
        wsp[1] = make_float2(t01 * t2, t01 * t23);  // out2, out3
        wsp[2] = make_float2(t0 * t23, t0 * t3);    // out4, out5
        wsp[3] = make_float2(t0, t2);               // out6, out7
        wsp[4] = make_float2(t23, t3);              // out8, out9

        __syncwarp();

        // Warp's output span: 32 rows * 40B = 1280B contiguous = 80 float4.
        // Fully coalesced STG.128 (512B per instruction per warp).
        float4* o = out + (size_t)(tile0 + it) * 640 + warp * 80;
        o[lane]      = wsv[lane];
        o[lane + 32] = wsv[lane + 32];
        if (lane < 16)
            o[lane + 64] = wsv[lane + 64];

        __syncwarp();   // protect smem reuse next iteration
        v = vn;
    }
}

extern "C" void kernel_launch(void* const* d_in, const int* in_sizes, int n_in,
                              void* d_out, int out_size)
{
    const float4* x = (const float4*)d_in[0];
    float4* out = (float4*)d_out;

    const int n_rows = in_sizes[0] / 4;                      // 1048576
    const int grid = n_rows / (QFM_BLOCK * QFM_ITERS);       // 1024 CTAs

    qfm_kernel<<<grid, QFM_BLOCK>>>(x, out);
}